// round 2
// baseline (speedup 1.0000x reference)
#include <cuda_runtime.h>
#include <cstdint>
#include <cstddef>

#define BATCH 128
#define RR    196
#define ENCD  2048
#define ATTD  512
#define DECD  512
#define EMBD  512
#define VOC   10000
#define TSTEPS 20

// ---------------- device scratch (static allocation only) ----------------
__device__ float g_att1[BATCH * RR * ATTD];        // 12.8M floats
__device__ float g_mean[BATCH * ENCD];
__device__ float g_state[BATCH * 1024];            // [h | c] per row
__device__ float g_hproj[BATCH * 4608];            // [att2 | fbeta_pre | hWhh]
__device__ float g_alpha[BATCH * RR];
__device__ float g_ctx[BATCH * ENCD];
__device__ float g_gadd[BATCH * 2048];
__device__ float g_gates[BATCH * 2048];
__device__ float g_E[BATCH * TSTEPS * EMBD];
__device__ float g_embproj[BATCH * TSTEPS * 2048];
__device__ float g_Wcat[4608 * 512];
__device__ float g_bcat[4608];
__device__ float g_bsum[2048];
__device__ float g_Winit[1024 * ENCD];
__device__ float g_binit[1024];

// ---------------- helpers ----------------
__device__ __forceinline__ float f2tf32(float x) {
    float r;
    asm("cvt.rna.tf32.f32 %0, %1;" : "=f"(r) : "f"(x));
    return r;
}

#define MMA_TF32(c, a, b0, b1)                                              \
    asm volatile(                                                           \
        "mma.sync.aligned.m16n8k8.row.col.f32.tf32.tf32.f32 "               \
        "{%0,%1,%2,%3}, {%4,%5,%6,%7}, {%8,%9}, {%0,%1,%2,%3};"             \
        : "+f"(c[0]), "+f"(c[1]), "+f"(c[2]), "+f"(c[3])                    \
        : "r"(a[0]), "r"(a[1]), "r"(a[2]), "r"(a[3]), "r"(b0), "r"(b1))

// C[M,N] = A[M,K] @ B[N,K]^T (+bias[N]) (+Csrc[M,N])
// PRECISE=true: fp32-faithful via tf32 hi/lo 3-pass. PRECISE=false: single tf32 pass.
template <bool PRECISE>
__global__ void gemm_tf32_kernel(const float* __restrict__ A, int lda,
                                 const float* __restrict__ Bm, int ldb,
                                 const float* __restrict__ bias,
                                 const float* __restrict__ Csrc, int ldsrc,
                                 float* __restrict__ C, int ldc,
                                 int M, int N, int K) {
    __shared__ float Ah[64][36];
    __shared__ float Bh[64][36];
    __shared__ float Al[PRECISE ? 64 : 1][36];
    __shared__ float Bl[PRECISE ? 64 : 1][36];

    const int tid = threadIdx.x;  // 128 threads
    const int m0 = blockIdx.y * 64;
    const int n0 = blockIdx.x * 64;

    const int warp = tid >> 5, lane = tid & 31;
    const int g = lane >> 2, tg = lane & 3;
    const int wm = (warp >> 1) * 32, wn = (warp & 1) * 32;

    float acc[2][4][4];
#pragma unroll
    for (int mi = 0; mi < 2; mi++)
#pragma unroll
        for (int ni = 0; ni < 4; ni++)
#pragma unroll
            for (int j = 0; j < 4; j++) acc[mi][ni][j] = 0.f;

    for (int kt = 0; kt < K; kt += 32) {
        if (kt) __syncthreads();
        // stage A and B tiles (64 rows x 32 k) with tf32 rounding (+ residual)
#pragma unroll
        for (int i = 0; i < 4; i++) {
            int q = tid + i * 128;       // 0..511
            int r = q >> 3;
            int kq = (q & 7) << 2;
            // A
            float4 v = make_float4(0.f, 0.f, 0.f, 0.f);
            int row = m0 + r;
            if (row < M) v = *(const float4*)(A + (size_t)row * lda + kt + kq);
            float4 h4;
            h4.x = f2tf32(v.x); h4.y = f2tf32(v.y); h4.z = f2tf32(v.z); h4.w = f2tf32(v.w);
            *(float4*)&Ah[r][kq] = h4;
            if (PRECISE) {
                float4 l4;
                l4.x = f2tf32(v.x - h4.x); l4.y = f2tf32(v.y - h4.y);
                l4.z = f2tf32(v.z - h4.z); l4.w = f2tf32(v.w - h4.w);
                *(float4*)&Al[r][kq] = l4;
            }
            // B
            float4 w = make_float4(0.f, 0.f, 0.f, 0.f);
            int rowb = n0 + r;
            if (rowb < N) w = *(const float4*)(Bm + (size_t)rowb * ldb + kt + kq);
            float4 hb;
            hb.x = f2tf32(w.x); hb.y = f2tf32(w.y); hb.z = f2tf32(w.z); hb.w = f2tf32(w.w);
            *(float4*)&Bh[r][kq] = hb;
            if (PRECISE) {
                float4 lb;
                lb.x = f2tf32(w.x - hb.x); lb.y = f2tf32(w.y - hb.y);
                lb.z = f2tf32(w.z - hb.z); lb.w = f2tf32(w.w - hb.w);
                *(float4*)&Bl[r][kq] = lb;
            }
        }
        __syncthreads();

#pragma unroll
        for (int ks = 0; ks < 4; ks++) {
            const int k0 = ks * 8;
            unsigned ah[2][4], al[2][4];
#pragma unroll
            for (int mi = 0; mi < 2; mi++) {
                int r = wm + mi * 16;
                ah[mi][0] = __float_as_uint(Ah[r + g][k0 + tg]);
                ah[mi][1] = __float_as_uint(Ah[r + g + 8][k0 + tg]);
                ah[mi][2] = __float_as_uint(Ah[r + g][k0 + tg + 4]);
                ah[mi][3] = __float_as_uint(Ah[r + g + 8][k0 + tg + 4]);
                if (PRECISE) {
                    al[mi][0] = __float_as_uint(Al[r + g][k0 + tg]);
                    al[mi][1] = __float_as_uint(Al[r + g + 8][k0 + tg]);
                    al[mi][2] = __float_as_uint(Al[r + g][k0 + tg + 4]);
                    al[mi][3] = __float_as_uint(Al[r + g + 8][k0 + tg + 4]);
                }
            }
#pragma unroll
            for (int ni = 0; ni < 4; ni++) {
                int cb = wn + ni * 8;
                unsigned bh0 = __float_as_uint(Bh[cb + g][k0 + tg]);
                unsigned bh1 = __float_as_uint(Bh[cb + g][k0 + tg + 4]);
#pragma unroll
                for (int mi = 0; mi < 2; mi++) MMA_TF32(acc[mi][ni], ah[mi], bh0, bh1);
                if (PRECISE) {
                    unsigned bl0 = __float_as_uint(Bl[cb + g][k0 + tg]);
                    unsigned bl1 = __float_as_uint(Bl[cb + g][k0 + tg + 4]);
#pragma unroll
                    for (int mi = 0; mi < 2; mi++) {
                        MMA_TF32(acc[mi][ni], al[mi], bh0, bh1);
                        MMA_TF32(acc[mi][ni], ah[mi], bl0, bl1);
                    }
                }
            }
        }
    }

    // epilogue
#pragma unroll
    for (int mi = 0; mi < 2; mi++) {
#pragma unroll
        for (int ni = 0; ni < 4; ni++) {
            int r0 = m0 + wm + mi * 16 + g;
            int c0 = n0 + wn + ni * 8 + tg * 2;
#pragma unroll
            for (int half = 0; half < 2; half++) {
                int rr = r0 + half * 8;
                if (rr >= M) continue;
#pragma unroll
                for (int j = 0; j < 2; j++) {
                    int cc = c0 + j;
                    if (cc >= N) continue;
                    float v = acc[mi][ni][half * 2 + j];
                    if (bias) v += bias[cc];
                    if (Csrc) v += Csrc[(size_t)rr * ldsrc + cc];
                    C[(size_t)rr * ldc + cc] = v;
                }
            }
        }
    }
}

// ---------------- small kernels ----------------
__global__ void bsum_kernel(float* __restrict__ out, const float* __restrict__ a,
                            const float* __restrict__ b) {
    int i = blockIdx.x * blockDim.x + threadIdx.x;
    if (i < 2048) out[i] = a[i] + b[i];
}

__global__ void gather_kernel(const int* __restrict__ cap, const float* __restrict__ table,
                              float* __restrict__ E) {
    int bt = blockIdx.x;            // 0..2559
    int b = bt / TSTEPS, tt = bt % TSTEPS;
    int idx = cap[b * (TSTEPS + 1) + tt];
    const float4* src = (const float4*)(table + (size_t)idx * EMBD);
    float4* dst = (float4*)(E + (size_t)bt * EMBD);
    dst[threadIdx.x] = src[threadIdx.x];  // 128 threads * float4 = 512 floats
}

__global__ void mean_kernel(const float* __restrict__ enc, float* __restrict__ mean) {
    int b = blockIdx.y;
    int e = blockIdx.x * 256 + threadIdx.x;
    const float* ep = enc + (size_t)b * RR * ENCD + e;
    float acc = 0.f;
#pragma unroll 4
    for (int r = 0; r < RR; r++) acc += ep[(size_t)r * ENCD];
    mean[b * ENCD + e] = acc * (1.f / (float)RR);
}

__global__ void attention_kernel(const float* __restrict__ att1,
                                 const float* __restrict__ hproj,
                                 const float* __restrict__ wfull,
                                 const float* __restrict__ bfull,
                                 float* __restrict__ alpha_out,
                                 float* __restrict__ out_alpha, int t) {
    int b = blockIdx.x;
    int tid = threadIdx.x;  // 256
    __shared__ float s_att2[512], s_wf[512], s_sc[RR], s_red[8];
    for (int i = tid; i < 512; i += 256) {
        s_att2[i] = hproj[b * 4608 + i];
        s_wf[i] = wfull[i];
    }
    __syncthreads();
    int warp = tid >> 5, lane = tid & 31;
    float bf = bfull[0];
    for (int r = warp; r < RR; r += 8) {
        const float* ap = att1 + ((size_t)(b * RR + r)) * 512;
        float s = 0.f;
#pragma unroll 4
        for (int a = lane; a < 512; a += 32) {
            float v = ap[a] + s_att2[a];
            s += fmaxf(v, 0.f) * s_wf[a];
        }
#pragma unroll
        for (int o = 16; o; o >>= 1) s += __shfl_xor_sync(0xffffffffu, s, o);
        if (lane == 0) s_sc[r] = s + bf;
    }
    __syncthreads();
    // softmax over RR
    float m = -1e30f;
    for (int i = tid; i < RR; i += 256) m = fmaxf(m, s_sc[i]);
#pragma unroll
    for (int o = 16; o; o >>= 1) m = fmaxf(m, __shfl_xor_sync(0xffffffffu, m, o));
    if (lane == 0) s_red[warp] = m;
    __syncthreads();
    m = s_red[0];
#pragma unroll
    for (int w = 1; w < 8; w++) m = fmaxf(m, s_red[w]);
    __syncthreads();
    float sum = 0.f;
    for (int i = tid; i < RR; i += 256) {
        float e = expf(s_sc[i] - m);
        s_sc[i] = e;
        sum += e;
    }
#pragma unroll
    for (int o = 16; o; o >>= 1) sum += __shfl_xor_sync(0xffffffffu, sum, o);
    if (lane == 0) s_red[warp] = sum;
    __syncthreads();
    sum = 0.f;
#pragma unroll
    for (int w = 0; w < 8; w++) sum += s_red[w];
    float inv = 1.f / sum;
    for (int i = tid; i < RR; i += 256) {
        float a = s_sc[i] * inv;
        alpha_out[b * RR + i] = a;
        out_alpha[((size_t)b * TSTEPS + t) * RR + i] = a;
    }
}

__global__ void ctx_kernel(const float* __restrict__ enc, const float* __restrict__ alpha,
                           const float* __restrict__ hproj, const float* __restrict__ embproj,
                           float* __restrict__ ctx, float* __restrict__ gadd, int t) {
    int b = blockIdx.y;
    int e = blockIdx.x * 256 + threadIdx.x;
    __shared__ float s_a[RR];
    for (int i = threadIdx.x; i < RR; i += 256) s_a[i] = alpha[b * RR + i];
    __syncthreads();
    const float* ep = enc + (size_t)b * RR * ENCD + e;
    float acc = 0.f;
#pragma unroll 4
    for (int r = 0; r < RR; r++) acc += s_a[r] * ep[(size_t)r * ENCD];
    float gpre = hproj[b * 4608 + 512 + e];
    float gate = 1.f / (1.f + expf(-gpre));
    ctx[b * ENCD + e] = gate * acc;
    gadd[b * 2048 + e] = embproj[((size_t)b * TSTEPS + t) * 2048 + e] + hproj[b * 4608 + 2560 + e];
}

__global__ void lstm_kernel(const float* __restrict__ gates, float* __restrict__ state) {
    int b = blockIdx.x, d = threadIdx.x;  // 512 threads
    const float* gt = gates + b * 2048;
    float i_ = 1.f / (1.f + expf(-gt[d]));
    float f_ = 1.f / (1.f + expf(-gt[512 + d]));
    float g_ = tanhf(gt[1024 + d]);
    float o_ = 1.f / (1.f + expf(-gt[1536 + d]));
    float c = state[b * 1024 + 512 + d];
    float cn = f_ * c + i_ * g_;
    float hn = o_ * tanhf(cn);
    state[b * 1024 + d] = hn;
    state[b * 1024 + 512 + d] = cn;
}

// ---------------- host ----------------
static float* symaddr(const void* sym) {
    void* p = nullptr;
    cudaGetSymbolAddress(&p, sym);
    return (float*)p;
}

static void launch_gemm(bool precise, const float* A, int lda, const float* B, int ldb,
                        const float* bias, const float* Csrc, int ldsrc, float* C, int ldc,
                        int M, int N, int K) {
    dim3 grid((N + 63) / 64, (M + 63) / 64);
    if (precise)
        gemm_tf32_kernel<true><<<grid, 128>>>(A, lda, B, ldb, bias, Csrc, ldsrc, C, ldc, M, N, K);
    else
        gemm_tf32_kernel<false><<<grid, 128>>>(A, lda, B, ldb, bias, Csrc, ldsrc, C, ldc, M, N, K);
}

extern "C" void kernel_launch(void* const* d_in, const int* in_sizes, int n_in,
                              void* d_out, int out_size) {
    const float* enc       = (const float*)d_in[0];
    const int*   captions  = (const int*)d_in[1];
    const float* W_enc_att = (const float*)d_in[2];
    const float* b_enc_att = (const float*)d_in[3];
    const float* W_dec_att = (const float*)d_in[4];
    const float* b_dec_att = (const float*)d_in[5];
    const float* W_full    = (const float*)d_in[6];
    const float* b_full    = (const float*)d_in[7];
    const float* emb_table = (const float*)d_in[8];
    const float* W_ih      = (const float*)d_in[9];
    const float* W_hh      = (const float*)d_in[10];
    const float* b_ih      = (const float*)d_in[11];
    const float* b_hh      = (const float*)d_in[12];
    const float* W_init_h  = (const float*)d_in[13];
    const float* b_init_h  = (const float*)d_in[14];
    const float* W_init_c  = (const float*)d_in[15];
    const float* b_init_c  = (const float*)d_in[16];
    const float* W_fbeta   = (const float*)d_in[17];
    const float* b_fbeta   = (const float*)d_in[18];
    const float* W_fc      = (const float*)d_in[19];
    const float* b_fc      = (const float*)d_in[20];

    float* out_pred  = (float*)d_out;
    float* out_alpha = out_pred + (size_t)BATCH * TSTEPS * VOC;

    float* att1   = symaddr(g_att1);
    float* meanb  = symaddr(g_mean);
    float* state  = symaddr(g_state);
    float* hproj  = symaddr(g_hproj);
    float* alpha  = symaddr(g_alpha);
    float* ctx    = symaddr(g_ctx);
    float* gadd   = symaddr(g_gadd);
    float* gates  = symaddr(g_gates);
    float* E      = symaddr(g_E);
    float* embprj = symaddr(g_embproj);
    float* Wcat   = symaddr(g_Wcat);
    float* bcat   = symaddr(g_bcat);
    float* bsum   = symaddr(g_bsum);
    float* Winit  = symaddr(g_Winit);
    float* binit  = symaddr(g_binit);

    // ---- prologue: weight concats (D2D copies are graph-capturable) ----
    cudaMemcpyAsync(Wcat, W_dec_att, (size_t)512 * 512 * 4, cudaMemcpyDeviceToDevice, 0);
    cudaMemcpyAsync(Wcat + 512 * 512, W_fbeta, (size_t)2048 * 512 * 4, cudaMemcpyDeviceToDevice, 0);
    cudaMemcpyAsync(Wcat + 2560 * 512, W_hh, (size_t)2048 * 512 * 4, cudaMemcpyDeviceToDevice, 0);
    cudaMemcpyAsync(bcat, b_dec_att, 512 * 4, cudaMemcpyDeviceToDevice, 0);
    cudaMemcpyAsync(bcat + 512, b_fbeta, 2048 * 4, cudaMemcpyDeviceToDevice, 0);
    cudaMemsetAsync(bcat + 2560, 0, 2048 * 4, 0);
    cudaMemcpyAsync(Winit, W_init_h, (size_t)512 * 2048 * 4, cudaMemcpyDeviceToDevice, 0);
    cudaMemcpyAsync(Winit + (size_t)512 * 2048, W_init_c, (size_t)512 * 2048 * 4,
                    cudaMemcpyDeviceToDevice, 0);
    cudaMemcpyAsync(binit, b_init_h, 512 * 4, cudaMemcpyDeviceToDevice, 0);
    cudaMemcpyAsync(binit + 512, b_init_c, 512 * 4, cudaMemcpyDeviceToDevice, 0);

    bsum_kernel<<<8, 256>>>(bsum, b_ih, b_hh);
    mean_kernel<<<dim3(8, BATCH), 256>>>(enc, meanb);
    // state = [h0 | c0] = mean @ [W_init_h; W_init_c]^T + [b_init_h; b_init_c]
    launch_gemm(true, meanb, ENCD, Winit, ENCD, binit, nullptr, 0, state, 1024, BATCH, 1024, ENCD);
    gather_kernel<<<BATCH * TSTEPS, 128>>>(captions, emb_table, E);
    // emb projection for all timesteps: E @ W_ih[:, :512]^T + (b_ih + b_hh)
    launch_gemm(false, E, EMBD, W_ih, EMBD + ENCD, bsum, nullptr, 0, embprj, 2048,
                BATCH * TSTEPS, 2048, EMBD);
    // att1 = enc @ W_enc_att^T + b_enc_att   (25088 x 512, K=2048)
    launch_gemm(false, enc, ENCD, W_enc_att, ENCD, b_enc_att, nullptr, 0, att1, ATTD,
                BATCH * RR, ATTD, ENCD);

    // ---- recurrence ----
    for (int t = 0; t < TSTEPS; t++) {
        // hproj = h @ [W_dec_att; W_fbeta; W_hh]^T + [b_dec_att; b_fbeta; 0]
        launch_gemm(true, state, 1024, Wcat, 512, bcat, nullptr, 0, hproj, 4608,
                    BATCH, 4608, DECD);
        attention_kernel<<<BATCH, 256>>>(att1, hproj, W_full, b_full, alpha, out_alpha, t);
        ctx_kernel<<<dim3(8, BATCH), 256>>>(enc, alpha, hproj, embprj, ctx, gadd, t);
        // gates = ctx @ W_ih[:, 512:]^T + (embproj_t + hWhh)   (bias folded in embproj)
        launch_gemm(true, ctx, ENCD, W_ih + 512, EMBD + ENCD, nullptr, gadd, 2048, gates, 2048,
                    BATCH, 2048, ENCD);
        lstm_kernel<<<BATCH, 512>>>(gates, state);
        // pred = h_new @ W_fc^T + b_fc -> out[:, t, :]
        launch_gemm(true, state, 1024, W_fc, DECD, b_fc, nullptr, 0, out_pred + (size_t)t * VOC,
                    TSTEPS * VOC, BATCH, VOC, DECD);
    }
}